// round 8
// baseline (speedup 1.0000x reference)
#include <cuda_runtime.h>
#include <cuda_bf16.h>

#define N_NODES 100000
#define B_DIM   16

// Scratch: transposed x and accumulator, [N, B] layout so one edge's 16
// batch lanes are 64 contiguous bytes.
__device__ float g_xt[N_NODES * B_DIM];
__device__ float g_yt[N_NODES * B_DIM];

// ---------------------------------------------------------------------------
// Kernel 1: transpose x [B,N] -> g_xt [N,B], and zero g_yt (zeroing HERE,
// right before the edge kernel's atomics — proven load-bearing R2 vs R4).
// FROZEN at R6 form.
// ---------------------------------------------------------------------------
__global__ void __launch_bounds__(256)
transpose_zero_kernel(const float* __restrict__ x, int N) {
    __shared__ float tile[16][260];
    const int n0 = blockIdx.x * 256;
    const int tid = threadIdx.x;
    const int N4 = N >> 2;

    float4 v[4];
    #pragma unroll
    for (int p = 0; p < 4; p++) {
        int idx = p * 256 + tid;
        int b  = idx >> 6;
        int nq = idx & 63;
        int gq = (n0 >> 2) + nq;
        v[p] = make_float4(0.f, 0.f, 0.f, 0.f);
        if (gq < N4) v[p] = ((const float4*)x)[b * N4 + gq];
    }
    #pragma unroll
    for (int p = 0; p < 4; p++) {
        int idx = p * 256 + tid;
        int b  = idx >> 6;
        int nq = idx & 63;
        tile[b][4 * nq + 0] = v[p].x;
        tile[b][4 * nq + 1] = v[p].y;
        tile[b][4 * nq + 2] = v[p].z;
        tile[b][4 * nq + 3] = v[p].w;
    }
    __syncthreads();

    #pragma unroll
    for (int p = 0; p < 4; p++) {
        int t = p * 256 + tid;
        int n = t >> 2;
        int q = t & 3;
        int nn = n0 + n;
        if (nn < N) {
            float4 w;
            w.x = tile[4 * q + 0][n];
            w.y = tile[4 * q + 1][n];
            w.z = tile[4 * q + 2][n];
            w.w = tile[4 * q + 3][n];
            *(float4*)&g_xt[nn * B_DIM + 4 * q] = w;
            *(float4*)&g_yt[nn * B_DIM + 4 * q] = make_float4(0.f, 0.f, 0.f, 0.f);
        }
    }
}

// ---------------------------------------------------------------------------
// Kernel 2: edge stage — 4 tasks per thread (quarter-grid split) so four
// independent gathers are in flight before any dependent math. Each task
// keeps the proven (edge, batch-quad) mapping: 4 consecutive lanes share one
// contiguous 64B node row on both gather and RED.
// Launch guarantees: quarter % 256 == 0 and 4*quarter >= E*4, with
// quarter <= E (so task 0 index < T always; tasks 1..3 are guarded).
// ---------------------------------------------------------------------------
__global__ void __launch_bounds__(256)
edge_kernel(const int*   __restrict__ src_idx,
            const int*   __restrict__ dst_idx,
            const float* __restrict__ edge_alpha,
            const float* __restrict__ edge_w,
            const float* __restrict__ edge_b,
            int E, int quarter) {
    const int t0 = blockIdx.x * blockDim.x + threadIdx.x;
    if (t0 >= quarter) return;
    const int T = E * 4;

    int   s[4], d[4], eidx[4], qq[4];
    float w[4], bb[4], a[4];
    bool  act[4];
    float4 xv[4];

    // Phase 1: param loads for all 4 tasks (independent).
    #pragma unroll
    for (int k = 0; k < 4; k++) {
        int t = t0 + k * quarter;
        act[k] = (t < T);
        int e = act[k] ? (t >> 2) : 0;
        eidx[k] = e;
        qq[k] = t & 3;
        s[k]  = __ldg(&src_idx[e]);
        d[k]  = __ldg(&dst_idx[e]);
        w[k]  = __ldg(&edge_w[e]);
        bb[k] = __ldg(&edge_b[e]);
        a[k]  = __ldg(&edge_alpha[e]);
    }

    // Phase 2: all 4 gathers in flight.
    #pragma unroll
    for (int k = 0; k < 4; k++) {
        xv[k] = __ldg((const float4*)&g_xt[s[k] * B_DIM + 4 * qq[k]]);
    }

    // Phase 3: math + RED per task.
    #pragma unroll
    for (int k = 0; k < 4; k++) {
        if (!act[k]) continue;
        float l0 = fmaf(w[k], xv[k].x, bb[k]);
        float l1 = fmaf(w[k], xv[k].y, bb[k]);
        float l2 = fmaf(w[k], xv[k].z, bb[k]);
        float l3 = fmaf(w[k], xv[k].w, bb[k]);
        float h0, h1, h2, h3;
        asm("tanh.approx.f32 %0, %1;" : "=f"(h0) : "f"(l0));
        asm("tanh.approx.f32 %0, %1;" : "=f"(h1) : "f"(l1));
        asm("tanh.approx.f32 %0, %1;" : "=f"(h2) : "f"(l2));
        asm("tanh.approx.f32 %0, %1;" : "=f"(h3) : "f"(l3));
        float m0 = fmaf(a[k], h0 - l0, l0);
        float m1 = fmaf(a[k], h1 - l1, l1);
        float m2 = fmaf(a[k], h2 - l2, l2);
        float m3 = fmaf(a[k], h3 - l3, l3);
        size_t gaddr = __cvta_generic_to_global(&g_yt[d[k] * B_DIM + 4 * qq[k]]);
        asm volatile("red.global.add.v4.f32 [%0], {%1, %2, %3, %4};"
                     :: "l"(gaddr), "f"(m0), "f"(m1), "f"(m2), "f"(m3)
                     : "memory");
    }
}

// ---------------------------------------------------------------------------
// Kernel 3: node stage + transpose back. FROZEN at R6 form.
// ---------------------------------------------------------------------------
__global__ void __launch_bounds__(256)
node_kernel(const float* __restrict__ node_alpha,
            const float* __restrict__ node_w,
            const float* __restrict__ node_b,
            float* __restrict__ out, int N) {
    __shared__ float tile[16][260];
    const int n0 = blockIdx.x * 256;
    const int tid = threadIdx.x;
    const int N4 = N >> 2;

    float4 v[4];
    #pragma unroll
    for (int p = 0; p < 4; p++) {
        int t = p * 256 + tid;
        int n = t >> 2;
        int q = t & 3;
        int nn = n0 + n;
        v[p] = make_float4(0.f, 0.f, 0.f, 0.f);
        if (nn < N) v[p] = *(const float4*)&g_yt[nn * B_DIM + 4 * q];
    }
    #pragma unroll
    for (int p = 0; p < 4; p++) {
        int t = p * 256 + tid;
        int n = t >> 2;
        int q = t & 3;
        tile[4 * q + 0][n] = v[p].x;
        tile[4 * q + 1][n] = v[p].y;
        tile[4 * q + 2][n] = v[p].z;
        tile[4 * q + 3][n] = v[p].w;
    }
    __syncthreads();

    #pragma unroll
    for (int p = 0; p < 4; p++) {
        int idx = p * 256 + tid;
        int b  = idx >> 6;
        int nq = idx & 63;
        int gq = (n0 >> 2) + nq;
        if (gq < N4) {
            float4 r;
            #pragma unroll
            for (int k = 0; k < 4; k++) {
                int nl = 4 * nq + k;
                int ng = n0 + nl;
                float y   = tile[b][nl];
                float ww  = node_w[ng];
                float bb  = node_b[ng];
                float aa  = node_alpha[ng];
                float lin = fmaf(ww, y, bb);
                float th;
                asm("tanh.approx.f32 %0, %1;" : "=f"(th) : "f"(lin));
                ((float*)&r)[k] = fmaf(aa, th - lin, lin);
            }
            ((float4*)out)[b * N4 + gq] = r;
        }
    }
}

// ---------------------------------------------------------------------------
// Input order: x, src_idx, dst_idx, edge_alpha, edge_w, edge_b,
// node_alpha, node_w, node_b. Output: float32 [B, N].
// ---------------------------------------------------------------------------
extern "C" void kernel_launch(void* const* d_in, const int* in_sizes, int n_in,
                              void* d_out, int out_size) {
    const float* x          = (const float*)d_in[0];
    const int*   src_idx    = (const int*)  d_in[1];
    const int*   dst_idx    = (const int*)  d_in[2];
    const float* edge_alpha = (const float*)d_in[3];
    const float* edge_w     = (const float*)d_in[4];
    const float* edge_b     = (const float*)d_in[5];
    const float* node_alpha = (const float*)d_in[6];
    const float* node_w     = (const float*)d_in[7];
    const float* node_b     = (const float*)d_in[8];
    float* out = (float*)d_out;

    const int E = in_sizes[1];
    const int N = in_sizes[6];

    int n_tiles = (N + 255) / 256;

    transpose_zero_kernel<<<n_tiles, 256>>>(x, N);

    const int T = E * 4;
    // quarter: block-multiple, 4*quarter covers T, quarter <= T (E*4 >= 1024
    // here so task 0 is always in range; tasks 1..3 guarded by act[]).
    int quarter = ((T + 3) / 4 + 255) & ~255;
    int blocks = quarter / 256;
    edge_kernel<<<blocks, 256>>>(src_idx, dst_idx, edge_alpha,
                                 edge_w, edge_b, E, quarter);

    node_kernel<<<n_tiles, 256>>>(node_alpha, node_w, node_b, out, N);
}